// round 9
// baseline (speedup 1.0000x reference)
#include <cuda_runtime.h>
#include <cuda_bf16.h>

// Zim_67430986547716 — bbox mask + Gaussian point mask.
// R9: R8 main loop (u16x2 tropical min, 1 issue slot per pixel) with the
// prologue/epilogue slimmed:
//  - warp 0 stages pts (1 coalesced LDG.64/lane) -> spx/spy/sbias in shared
//  - warp 1 stages boxes (LDG.128) and precomputes bbox row/col indicator
//    floats; all other threads do ZERO global loads
//  - table build is pure shared+ALU; bbox epilogue = rowf * colf (LDS+FMUL)
// Cuts ~75 issue slots/thread and removes 10 serialized LDG chains/thread.

#define MASK_N 64
#define NPTS   32
#define INV_STRIDE (1.0f / 16.0f)
#define INV_2SIG2  (1.0f / 882.0f)   // 2*21*21

__global__ __launch_bounds__(256, 8)
void zim_masks_kernel(const float* __restrict__ boxes,
                      const float* __restrict__ pts,
                      float* __restrict__ bbox_out,
                      float* __restrict__ point_out)
{
    __shared__ unsigned int sdx2p[NPTS * 16];  // 2KB: [p][cpair] dx2 u16 pairs (quadrant cols)
    __shared__ unsigned int sdy2d[NPTS * 32];  // 4KB: [p][row] (dy2+bias) duplicated u16x2
    __shared__ int   spx[NPTS], spy[NPTS], sbias[NPTS];
    __shared__ float colf[32];                 // quadrant col in-bbox indicator
    __shared__ float rowf[32];                 // quadrant row in-bbox indicator

    const int b      = blockIdx.x;
    const int quad   = blockIdx.y;              // 0..3
    const int i_base = (quad >> 1) << 5;        // 0 or 32
    const int j_base = (quad & 1) << 5;         // 0 or 32
    const int tid    = threadIdx.x;

    if (tid < 32) {
        // ---- warp 0: stage point centers (one coalesced float2 per lane) ----
        const float2 xy = reinterpret_cast<const float2*>(pts)[b * NPTS + tid];
        const int px = (int)floorf(xy.x * INV_STRIDE);
        const int py = (int)floorf(xy.y * INV_STRIDE);
        const bool valid = (px >= 0) & (py >= 0) & (px < MASK_N) & (py < MASK_N);
        spx[tid]   = px;
        spy[tid]   = py;
        sbias[tid] = valid ? 0 : 30000;
    } else if (tid < 64) {
        // ---- warp 1: stage bbox indicator rows/cols for this quadrant ----
        const int l = tid - 32;                 // 0..31
        const float4 bx = reinterpret_cast<const float4*>(boxes)[b];
        const int xmin_i = max((int)floorf(fminf(bx.x, bx.z) * INV_STRIDE), 0);
        const int ymin_i = max((int)floorf(fminf(bx.y, bx.w) * INV_STRIDE), 0);
        const int xmax_i = min((int)floorf(fmaxf(bx.x, bx.z) * INV_STRIDE) + 1, MASK_N);
        const int ymax_i = min((int)floorf(fmaxf(bx.y, bx.w) * INV_STRIDE) + 1, MASK_N);
        const int j = j_base + l;
        const int i = i_base + l;
        colf[l] = ((j >= xmin_i) & (j < xmax_i)) ? 1.0f : 0.0f;
        rowf[l] = ((i >= ymin_i) & (i < ymax_i)) ? 1.0f : 0.0f;
    }
    __syncthreads();

    // ---- build u16 distance tables from staged values (pure LDS+ALU) ----
    #pragma unroll
    for (int k = tid; k < NPTS * 16; k += 256) {        // 2 iters: dx2 pairs
        const int p  = k >> 4;
        const int c0 = j_base + ((k & 15) << 1);
        const int d0 = c0 - spx[p];
        const int d1 = d0 + 1;
        sdx2p[k] = (unsigned int)(d0 * d0) | ((unsigned int)(d1 * d1) << 16);
    }
    #pragma unroll
    for (int k = tid; k < NPTS * 32; k += 256) {        // 4 iters: dy2+bias duplicated
        const int p = k >> 5;
        const int d = i_base + (k & 31) - spy[p];
        const unsigned int v = (unsigned int)(d * d + sbias[p]);
        sdy2d[k] = v | (v << 16);
    }
    __syncthreads();

    // ---- per-thread: 1 row x 4 cols, u16x2 SIMD min over 32 points ----
    const int il = tid >> 3;            // 0..31 local row
    const int cg = (tid & 7);           // col group: cols 4*cg .. 4*cg+3

    unsigned int m01 = 0xFFFFFFFFu, m23 = 0xFFFFFFFFu;

    const unsigned int* dyp = &sdy2d[il];
    const unsigned int* dxp = &sdx2p[cg * 2];

    #pragma unroll 8
    for (int p = 0; p < NPTS; p++) {
        const unsigned int dyd = dyp[p * 32];
        const uint2 dx = *reinterpret_cast<const uint2*>(dxp + p * 16);
        m01 = __viaddmin_u16x2(dyd, dx.x, m01);
        m23 = __viaddmin_u16x2(dyd, dx.y, m23);
    }

    // ---- one exp per pixel ----
    const float g0 = __expf((float)(m01 & 0xFFFFu) * -INV_2SIG2);
    const float g1 = __expf((float)(m01 >> 16)     * -INV_2SIG2);
    const float g2 = __expf((float)(m23 & 0xFFFFu) * -INV_2SIG2);
    const float g3 = __expf((float)(m23 >> 16)     * -INV_2SIG2);

    // ---- stores ----
    const int i = i_base + il;
    const int j = j_base + (cg << 2);
    const size_t base = (size_t)b * (MASK_N * MASK_N) + (size_t)i * MASK_N + j;

    *reinterpret_cast<float4*>(point_out + base) = make_float4(g0, g1, g2, g3);

    const float rf = rowf[il];
    const float4 cf = *reinterpret_cast<const float4*>(&colf[cg << 2]);
    *reinterpret_cast<float4*>(bbox_out + base) =
        make_float4(rf * cf.x, rf * cf.y, rf * cf.z, rf * cf.w);
}

extern "C" void kernel_launch(void* const* d_in, const int* in_sizes, int n_in,
                              void* d_out, int out_size) {
    const float* boxes = (const float*)d_in[0];   // 256*4
    const float* pts   = (const float*)d_in[1];   // 256*32*2
    float* out = (float*)d_out;                   // 2 * 256*64*64
    const int B = in_sizes[0] / 4;                // 256
    float* bbox_out  = out;
    float* point_out = out + (size_t)B * MASK_N * MASK_N;
    dim3 grid(B, 4);
    zim_masks_kernel<<<grid, 256>>>(boxes, pts, bbox_out, point_out);
}